// round 1
// baseline (speedup 1.0000x reference)
#include <cuda_runtime.h>

#define D_MODEL 1024
#define KV_DIM  256
#define L_SEQ   4096
#define HD      64
#define NHEADS  16

// Scratch (no allocations allowed): Q [4096,1024], K/V [4096,256], attn out [4096,1024]
__device__ float g_Q[L_SEQ * D_MODEL];
__device__ float g_K[L_SEQ * KV_DIM];
__device__ float g_V[L_SEQ * KV_DIM];
__device__ float g_A[L_SEQ * D_MODEL];

// ---------------------------------------------------------------------------
// C[M,N] = A[M,K] @ B[K,N] + bias.  Tiles: 64x64x16, 256 threads, 4x4 microtile.
// M % 64 == 0, N % 64 == 0, K % 16 == 0 (all true for our shapes).
// ---------------------------------------------------------------------------
__global__ __launch_bounds__(256) void sgemm_bias(
    const float* __restrict__ A, const float* __restrict__ B,
    const float* __restrict__ bias, float* __restrict__ C,
    int M, int N, int K)
{
    __shared__ float As[16][65];   // [k][m] transposed, padded
    __shared__ float Bs[16][64];   // [k][n]
    const int tid = threadIdx.x;
    const int tx = tid & 15, ty = tid >> 4;
    const int row0 = blockIdx.y * 64, col0 = blockIdx.x * 64;

    float acc[4][4] = {};
    for (int k0 = 0; k0 < K; k0 += 16) {
        #pragma unroll
        for (int i = 0; i < 4; i++) {
            int idx = tid + i * 256;
            int r  = idx >> 4, c  = idx & 15;   // A tile: 64 rows x 16 k
            As[c][r] = A[(row0 + r) * K + (k0 + c)];
            int rb = idx >> 6, cb = idx & 63;   // B tile: 16 k x 64 cols
            Bs[rb][cb] = B[(k0 + rb) * N + (col0 + cb)];
        }
        __syncthreads();
        #pragma unroll
        for (int kk = 0; kk < 16; kk++) {
            float a[4], b[4];
            #pragma unroll
            for (int m = 0; m < 4; m++) a[m] = As[kk][ty * 4 + m];
            #pragma unroll
            for (int n = 0; n < 4; n++) b[n] = Bs[kk][tx * 4 + n];
            #pragma unroll
            for (int m = 0; m < 4; m++)
                #pragma unroll
                for (int n = 0; n < 4; n++)
                    acc[m][n] += a[m] * b[n];
        }
        __syncthreads();
    }
    #pragma unroll
    for (int m = 0; m < 4; m++) {
        int r = row0 + ty * 4 + m;
        #pragma unroll
        for (int n = 0; n < 4; n++) {
            int c = col0 + tx * 4 + n;
            C[r * N + c] = acc[m][n] + bias[c];
        }
    }
}

// ---------------------------------------------------------------------------
// Flash attention (non-causal), fp32.
// grid = (L/64 q-tiles, 16 heads), 256 threads.
// Thread layout: row = tid>>2 (0..63 query rows), j = tid&3.
//   scores: each thread computes 8 key-cols (j*8+c) of its row for KT=32 keys
//   output: each thread accumulates 16 head dims (interleaved dv = 4*c + j)
// Online softmax with running (m, l).
// ---------------------------------------------------------------------------
__global__ __launch_bounds__(256) void gqa_attention()
{
    __shared__ float Qs[64][65];   // [row][d], padded
    __shared__ float Ks[64][33];   // [d][key], padded  (KT=32 keys)
    __shared__ float Vs[32][64];   // [key][d]
    __shared__ float Ps[64][33];   // [row][key], padded

    const int h   = blockIdx.y;
    const int kvh = h >> 2;                 // shared KV head (4 groups)
    const int q0  = blockIdx.x * 64;
    const int tid = threadIdx.x;
    const int row = tid >> 2;
    const int j   = tid & 3;

    // Load Q tile, pre-scaled by 1/sqrt(64)
    for (int i = tid; i < 64 * 64; i += 256) {
        int r = i >> 6, d = i & 63;
        Qs[r][d] = g_Q[(q0 + r) * D_MODEL + h * HD + d] * 0.125f;
    }

    float m_run = -1e30f, l_run = 0.f;
    float o[16];
    #pragma unroll
    for (int i = 0; i < 16; i++) o[i] = 0.f;
    __syncthreads();

    for (int k0 = 0; k0 < L_SEQ; k0 += 32) {
        // Load K (transposed [d][key]) and V tiles
        for (int i = tid; i < 32 * 64; i += 256) {
            int r = i >> 6, d = i & 63;
            Ks[d][r] = g_K[(k0 + r) * KV_DIM + kvh * HD + d];
            Vs[r][d] = g_V[(k0 + r) * KV_DIM + kvh * HD + d];
        }
        __syncthreads();

        // scores s[c] = (Q[row,:] . K[j*8+c,:]) / 8
        float s[8];
        #pragma unroll
        for (int c = 0; c < 8; c++) s[c] = 0.f;
        #pragma unroll 16
        for (int d = 0; d < 64; d++) {
            float qv = Qs[row][d];
            #pragma unroll
            for (int c = 0; c < 8; c++)
                s[c] += qv * Ks[d][j * 8 + c];
        }

        // row max across this thread's 8 cols + its 3 sibling lanes
        float mloc = s[0];
        #pragma unroll
        for (int c = 1; c < 8; c++) mloc = fmaxf(mloc, s[c]);
        mloc = fmaxf(mloc, __shfl_xor_sync(0xffffffffu, mloc, 1));
        mloc = fmaxf(mloc, __shfl_xor_sync(0xffffffffu, mloc, 2));

        float m_new = fmaxf(m_run, mloc);
        float corr  = __expf(m_run - m_new);
        float lsum  = 0.f;
        #pragma unroll
        for (int c = 0; c < 8; c++) { s[c] = __expf(s[c] - m_new); lsum += s[c]; }
        lsum += __shfl_xor_sync(0xffffffffu, lsum, 1);
        lsum += __shfl_xor_sync(0xffffffffu, lsum, 2);
        l_run = l_run * corr + lsum;
        m_run = m_new;

        #pragma unroll
        for (int i = 0; i < 16; i++) o[i] *= corr;

        // Exchange P within the row's 4 lanes via shared (same warp -> syncwarp)
        #pragma unroll
        for (int c = 0; c < 8; c++) Ps[row][j * 8 + c] = s[c];
        __syncwarp();

        // o[c] += sum_kc P[row,kc] * V[kc, 4c+j]
        #pragma unroll 8
        for (int kc = 0; kc < 32; kc++) {
            float p = Ps[row][kc];
            #pragma unroll
            for (int c = 0; c < 16; c++)
                o[c] += p * Vs[kc][c * 4 + j];
        }
        __syncthreads();   // protect Ks/Vs/Ps for next tile
    }

    float inv = 1.f / l_run;
    #pragma unroll
    for (int c = 0; c < 16; c++)
        g_A[(q0 + row) * D_MODEL + h * HD + c * 4 + j] = o[c] * inv;
}

// ---------------------------------------------------------------------------
extern "C" void kernel_launch(void* const* d_in, const int* in_sizes, int n_in,
                              void* d_out, int out_size)
{
    const float* x  = (const float*)d_in[0];
    const float* Wq = (const float*)d_in[1];
    const float* bq = (const float*)d_in[2];
    const float* Wk = (const float*)d_in[3];
    const float* bk = (const float*)d_in[4];
    const float* Wv = (const float*)d_in[5];
    const float* bv = (const float*)d_in[6];
    const float* Wo = (const float*)d_in[7];
    const float* bo = (const float*)d_in[8];
    float* out = (float*)d_out;

    float *Qp, *Kp, *Vp, *Ap;
    cudaGetSymbolAddress((void**)&Qp, g_Q);
    cudaGetSymbolAddress((void**)&Kp, g_K);
    cudaGetSymbolAddress((void**)&Vp, g_V);
    cudaGetSymbolAddress((void**)&Ap, g_A);

    dim3 blk(256);
    // Projections
    sgemm_bias<<<dim3(D_MODEL / 64, L_SEQ / 64), blk>>>(x, Wq, bq, Qp, L_SEQ, D_MODEL, D_MODEL);
    sgemm_bias<<<dim3(KV_DIM  / 64, L_SEQ / 64), blk>>>(x, Wk, bk, Kp, L_SEQ, KV_DIM,  D_MODEL);
    sgemm_bias<<<dim3(KV_DIM  / 64, L_SEQ / 64), blk>>>(x, Wv, bv, Vp, L_SEQ, KV_DIM,  D_MODEL);
    // Attention
    gqa_attention<<<dim3(L_SEQ / 64, NHEADS), blk>>>();
    // Output projection
    sgemm_bias<<<dim3(D_MODEL / 64, L_SEQ / 64), blk>>>(Ap, Wo, bo, out, L_SEQ, D_MODEL, D_MODEL);
}

// round 3
// speedup vs baseline: 3.7072x; 3.7072x over previous
#include <cuda_runtime.h>
#include <cstdint>

#define D_MODEL 1024
#define KV_DIM  256
#define L_SEQ   4096
#define HD      64
#define NHEADS  16

// Scratch (no allocations allowed)
__device__ float g_Q[L_SEQ * D_MODEL];
__device__ float g_K[L_SEQ * KV_DIM];
__device__ float g_V[L_SEQ * KV_DIM];
__device__ float g_A[L_SEQ * D_MODEL];

// cvt.rna.tf32.f32 needs a .b32 destination register
__device__ __forceinline__ uint32_t to_tf32(float x) {
    uint32_t y;
    asm("cvt.rna.tf32.f32 %0, %1;" : "=r"(y) : "f"(x));
    return y;
}

__device__ __forceinline__ void mma_tf32(float c[4], const uint32_t a[4], const uint32_t b[2]) {
    asm volatile("mma.sync.aligned.m16n8k8.row.col.f32.tf32.tf32.f32 "
        "{%0,%1,%2,%3},{%4,%5,%6,%7},{%8,%9},{%0,%1,%2,%3};"
        : "+f"(c[0]), "+f"(c[1]), "+f"(c[2]), "+f"(c[3])
        : "r"(a[0]), "r"(a[1]), "r"(a[2]), "r"(a[3]), "r"(b[0]), "r"(b[1]));
}

// ---------------------------------------------------------------------------
// C[M,N] = A[M,K] @ B[K,N] + bias,  tf32 tensor cores.
// Block tile 128x64, 256 threads = 8 warps (4 m x 2 n), warp tile 32x32.
// ---------------------------------------------------------------------------
__global__ __launch_bounds__(256) void gemm_tf32(
    const float* __restrict__ A, const float* __restrict__ B,
    const float* __restrict__ bias, float* __restrict__ C,
    int M, int N, int K)
{
    __shared__ uint32_t As[16][136];   // [k][m], width%32==8 -> conflict-free frags
    __shared__ uint32_t Bs[16][72];    // [k][n], width%32==8

    const int tid = threadIdx.x;
    const int lane = tid & 31, wid = tid >> 5;
    const int wm = wid >> 1, wn = wid & 1;
    const int row0 = blockIdx.y * 128, col0 = blockIdx.x * 64;
    const int lr = lane >> 2, lc = lane & 3;

    float acc[2][4][4] = {};
    for (int k0 = 0; k0 < K; k0 += 16) {
        #pragma unroll
        for (int i = 0; i < 2; i++) {
            int idx4 = tid + i * 256;                 // 512 float4 of A tile
            int r = idx4 >> 2, c4 = (idx4 & 3) * 4;
            const float4 v = *(const float4*)&A[(row0 + r) * K + k0 + c4];
            As[c4+0][r] = to_tf32(v.x);
            As[c4+1][r] = to_tf32(v.y);
            As[c4+2][r] = to_tf32(v.z);
            As[c4+3][r] = to_tf32(v.w);
        }
        {
            int rb = tid >> 4, cb = (tid & 15) * 4;   // 256 float4 of B tile
            const float4 v = *(const float4*)&B[(k0 + rb) * N + col0 + cb];
            Bs[rb][cb+0] = to_tf32(v.x);
            Bs[rb][cb+1] = to_tf32(v.y);
            Bs[rb][cb+2] = to_tf32(v.z);
            Bs[rb][cb+3] = to_tf32(v.w);
        }
        __syncthreads();
        #pragma unroll
        for (int ks = 0; ks < 2; ks++) {
            uint32_t a[2][4], b[4][2];
            #pragma unroll
            for (int mi = 0; mi < 2; mi++) {
                int m0 = wm * 32 + mi * 16;
                a[mi][0] = As[ks*8 + lc    ][m0 + lr    ];
                a[mi][1] = As[ks*8 + lc    ][m0 + lr + 8];
                a[mi][2] = As[ks*8 + lc + 4][m0 + lr    ];
                a[mi][3] = As[ks*8 + lc + 4][m0 + lr + 8];
            }
            #pragma unroll
            for (int ni = 0; ni < 4; ni++) {
                int n0 = wn * 32 + ni * 8;
                b[ni][0] = Bs[ks*8 + lc    ][n0 + lr];
                b[ni][1] = Bs[ks*8 + lc + 4][n0 + lr];
            }
            #pragma unroll
            for (int mi = 0; mi < 2; mi++)
                #pragma unroll
                for (int ni = 0; ni < 4; ni++)
                    mma_tf32(acc[mi][ni], a[mi], b[ni]);
        }
        __syncthreads();
    }
    #pragma unroll
    for (int mi = 0; mi < 2; mi++) {
        #pragma unroll
        for (int ni = 0; ni < 4; ni++) {
            int r = row0 + wm*32 + mi*16 + lr;
            int c = col0 + wn*32 + ni*8 + 2*lc;
            C[r*N + c]         = acc[mi][ni][0] + bias[c];
            C[r*N + c + 1]     = acc[mi][ni][1] + bias[c+1];
            C[(r+8)*N + c]     = acc[mi][ni][2] + bias[c];
            C[(r+8)*N + c + 1] = acc[mi][ni][3] + bias[c+1];
        }
    }
}

// ---------------------------------------------------------------------------
// Flash attention, tf32 tensor cores.
// grid = (64 q-tiles, 16 heads), 128 threads = 4 warps; warp owns 16 q-rows.
// Q fragments held in registers for the whole kernel. KT = 32 keys per step.
// ---------------------------------------------------------------------------
__global__ __launch_bounds__(128) void gqa_attn_tf32()
{
    __shared__ uint32_t Ks[64][40];   // [d][key]  width%32==8 -> conflict-free B-frags
    __shared__ uint32_t Vs[32][72];   // [key][d]  width%32==8
    __shared__ uint32_t Ps[64][36];   // [row][key] width%32==4 -> conflict-free A-frags

    const int h = blockIdx.y, kvh = h >> 2;
    const int q0 = blockIdx.x * 64;
    const int tid = threadIdx.x;
    const int lane = tid & 31, wid = tid >> 5;
    const int lr = lane >> 2, lc = lane & 3;
    const int m_base = wid * 16;

    // Q fragments (pre-scaled by 1/sqrt(64), tf32-rounded); 8 k-steps over d=64
    uint32_t qa[8][4];
    {
        const float* Qb = g_Q + (q0 + m_base) * D_MODEL + h * HD;
        #pragma unroll
        for (int ks = 0; ks < 8; ks++) {
            qa[ks][0] = to_tf32(Qb[(lr    )*D_MODEL + ks*8 + lc    ] * 0.125f);
            qa[ks][1] = to_tf32(Qb[(lr + 8)*D_MODEL + ks*8 + lc    ] * 0.125f);
            qa[ks][2] = to_tf32(Qb[(lr    )*D_MODEL + ks*8 + lc + 4] * 0.125f);
            qa[ks][3] = to_tf32(Qb[(lr + 8)*D_MODEL + ks*8 + lc + 4] * 0.125f);
        }
    }

    float o[8][4] = {};
    float m0 = -1e30f, m1 = -1e30f, l0 = 0.f, l1 = 0.f;

    for (int k0 = 0; k0 < L_SEQ; k0 += 32) {
        // Load K (transposed [d][key]) and V ([key][d]), tf32-rounded
        #pragma unroll
        for (int i = 0; i < 4; i++) {
            int idx4 = tid + i * 128;                 // 512 float4 per array
            int key = idx4 >> 4, d4 = (idx4 & 15) * 4;
            const float4 kv = *(const float4*)&g_K[(k0 + key) * KV_DIM + kvh*HD + d4];
            Ks[d4+0][key] = to_tf32(kv.x);
            Ks[d4+1][key] = to_tf32(kv.y);
            Ks[d4+2][key] = to_tf32(kv.z);
            Ks[d4+3][key] = to_tf32(kv.w);
            const float4 vv = *(const float4*)&g_V[(k0 + key) * KV_DIM + kvh*HD + d4];
            Vs[key][d4+0] = to_tf32(vv.x);
            Vs[key][d4+1] = to_tf32(vv.y);
            Vs[key][d4+2] = to_tf32(vv.z);
            Vs[key][d4+3] = to_tf32(vv.w);
        }
        __syncthreads();

        // S = Q @ K^T   (16 x 32 per warp)
        float s[4][4] = {};
        #pragma unroll
        for (int ks = 0; ks < 8; ks++) {
            uint32_t b[4][2];
            #pragma unroll
            for (int nt = 0; nt < 4; nt++) {
                b[nt][0] = Ks[ks*8 + lc    ][nt*8 + lr];
                b[nt][1] = Ks[ks*8 + lc + 4][nt*8 + lr];
            }
            #pragma unroll
            for (int nt = 0; nt < 4; nt++)
                mma_tf32(s[nt], qa[ks], b[nt]);
        }

        // Online softmax on C-fragment layout (rows lr, lr+8)
        float mx0 = s[0][0], mx1 = s[0][2];
        #pragma unroll
        for (int nt = 0; nt < 4; nt++) {
            mx0 = fmaxf(mx0, fmaxf(s[nt][0], s[nt][1]));
            mx1 = fmaxf(mx1, fmaxf(s[nt][2], s[nt][3]));
        }
        mx0 = fmaxf(mx0, __shfl_xor_sync(~0u, mx0, 1));
        mx0 = fmaxf(mx0, __shfl_xor_sync(~0u, mx0, 2));
        mx1 = fmaxf(mx1, __shfl_xor_sync(~0u, mx1, 1));
        mx1 = fmaxf(mx1, __shfl_xor_sync(~0u, mx1, 2));
        float nm0 = fmaxf(m0, mx0), nm1 = fmaxf(m1, mx1);
        float cr0 = __expf(m0 - nm0), cr1 = __expf(m1 - nm1);
        float ls0 = 0.f, ls1 = 0.f;
        #pragma unroll
        for (int nt = 0; nt < 4; nt++) {
            s[nt][0] = __expf(s[nt][0] - nm0); ls0 += s[nt][0];
            s[nt][1] = __expf(s[nt][1] - nm0); ls0 += s[nt][1];
            s[nt][2] = __expf(s[nt][2] - nm1); ls1 += s[nt][2];
            s[nt][3] = __expf(s[nt][3] - nm1); ls1 += s[nt][3];
        }
        ls0 += __shfl_xor_sync(~0u, ls0, 1); ls0 += __shfl_xor_sync(~0u, ls0, 2);
        ls1 += __shfl_xor_sync(~0u, ls1, 1); ls1 += __shfl_xor_sync(~0u, ls1, 2);
        l0 = l0 * cr0 + ls0; l1 = l1 * cr1 + ls1;
        m0 = nm0; m1 = nm1;
        #pragma unroll
        for (int nt = 0; nt < 8; nt++) {
            o[nt][0] *= cr0; o[nt][1] *= cr0; o[nt][2] *= cr1; o[nt][3] *= cr1;
        }

        // Stage P in this warp's private Ps rows (warp-local exchange only)
        #pragma unroll
        for (int nt = 0; nt < 4; nt++) {
            Ps[m_base + lr    ][nt*8 + 2*lc    ] = to_tf32(s[nt][0]);
            Ps[m_base + lr    ][nt*8 + 2*lc + 1] = to_tf32(s[nt][1]);
            Ps[m_base + lr + 8][nt*8 + 2*lc    ] = to_tf32(s[nt][2]);
            Ps[m_base + lr + 8][nt*8 + 2*lc + 1] = to_tf32(s[nt][3]);
        }
        __syncwarp();

        // O += P @ V   (16 x 64 per warp, k=32)
        #pragma unroll
        for (int ks = 0; ks < 4; ks++) {
            uint32_t a[4];
            a[0] = Ps[m_base + lr    ][ks*8 + lc    ];
            a[1] = Ps[m_base + lr + 8][ks*8 + lc    ];
            a[2] = Ps[m_base + lr    ][ks*8 + lc + 4];
            a[3] = Ps[m_base + lr + 8][ks*8 + lc + 4];
            #pragma unroll
            for (int nt = 0; nt < 8; nt++) {
                uint32_t b[2];
                b[0] = Vs[ks*8 + lc    ][nt*8 + lr];
                b[1] = Vs[ks*8 + lc + 4][nt*8 + lr];
                mma_tf32(o[nt], a, b);
            }
        }
        __syncthreads();
    }

    float inv0 = 1.f / l0, inv1 = 1.f / l1;
    float* Ob = g_A + (q0 + m_base) * D_MODEL + h * HD;
    #pragma unroll
    for (int nt = 0; nt < 8; nt++) {
        Ob[(lr    )*D_MODEL + nt*8 + 2*lc    ] = o[nt][0] * inv0;
        Ob[(lr    )*D_MODEL + nt*8 + 2*lc + 1] = o[nt][1] * inv0;
        Ob[(lr + 8)*D_MODEL + nt*8 + 2*lc    ] = o[nt][2] * inv1;
        Ob[(lr + 8)*D_MODEL + nt*8 + 2*lc + 1] = o[nt][3] * inv1;
    }
}

// ---------------------------------------------------------------------------
extern "C" void kernel_launch(void* const* d_in, const int* in_sizes, int n_in,
                              void* d_out, int out_size)
{
    const float* x  = (const float*)d_in[0];
    const float* Wq = (const float*)d_in[1];
    const float* bq = (const float*)d_in[2];
    const float* Wk = (const float*)d_in[3];
    const float* bk = (const float*)d_in[4];
    const float* Wv = (const float*)d_in[5];
    const float* bv = (const float*)d_in[6];
    const float* Wo = (const float*)d_in[7];
    const float* bo = (const float*)d_in[8];
    float* out = (float*)d_out;

    float *Qp, *Kp, *Vp, *Ap;
    cudaGetSymbolAddress((void**)&Qp, g_Q);
    cudaGetSymbolAddress((void**)&Kp, g_K);
    cudaGetSymbolAddress((void**)&Vp, g_V);
    cudaGetSymbolAddress((void**)&Ap, g_A);

    // Projections
    gemm_tf32<<<dim3(D_MODEL/64, L_SEQ/128), 256>>>(x, Wq, bq, Qp, L_SEQ, D_MODEL, D_MODEL);
    gemm_tf32<<<dim3(KV_DIM /64, L_SEQ/128), 256>>>(x, Wk, bk, Kp, L_SEQ, KV_DIM,  D_MODEL);
    gemm_tf32<<<dim3(KV_DIM /64, L_SEQ/128), 256>>>(x, Wv, bv, Vp, L_SEQ, KV_DIM,  D_MODEL);
    // Attention
    gqa_attn_tf32<<<dim3(L_SEQ/64, NHEADS), 128>>>();
    // Output projection
    gemm_tf32<<<dim3(D_MODEL/64, L_SEQ/128), 256>>>(Ap, Wo, bo, out, L_SEQ, D_MODEL, D_MODEL);
}

// round 4
// speedup vs baseline: 6.9120x; 1.8645x over previous
#include <cuda_runtime.h>
#include <cstdint>

#define D_MODEL 1024
#define KV_DIM  256
#define L_SEQ   4096
#define HD      64
#define NHEADS  16

// Scratch (device globals; no allocations allowed)
__device__ float g_X32 [L_SEQ * D_MODEL];   // tf32-rounded x
__device__ float g_Wq32[D_MODEL * D_MODEL];
__device__ float g_Wk32[D_MODEL * KV_DIM];
__device__ float g_Wv32[D_MODEL * KV_DIM];
__device__ float g_Wo32[D_MODEL * D_MODEL];
__device__ float g_Q [L_SEQ * D_MODEL];     // rounded + pre-scaled by 0.125
__device__ float g_Kt[KV_DIM * L_SEQ];      // K^T, rounded: [kvh*64+d][l]
__device__ float g_V [L_SEQ * KV_DIM];      // rounded
__device__ float g_A [L_SEQ * D_MODEL];     // attention out, rounded

__device__ __forceinline__ uint32_t to_tf32(float x) {
    uint32_t y;
    asm("cvt.rna.tf32.f32 %0, %1;" : "=r"(y) : "f"(x));
    return y;
}
__device__ __forceinline__ float to_tf32f(float x) { return __uint_as_float(to_tf32(x)); }

__device__ __forceinline__ void mma_tf32(float c[4], const uint32_t a[4], const uint32_t b[2]) {
    asm volatile("mma.sync.aligned.m16n8k8.row.col.f32.tf32.tf32.f32 "
        "{%0,%1,%2,%3},{%4,%5,%6,%7},{%8,%9},{%0,%1,%2,%3};"
        : "+f"(c[0]), "+f"(c[1]), "+f"(c[2]), "+f"(c[3])
        : "r"(a[0]), "r"(a[1]), "r"(a[2]), "r"(a[3]), "r"(b[0]), "r"(b[1]));
}

__device__ __forceinline__ void cp16(void* smem, const void* gmem) {
    uint32_t s = (uint32_t)__cvta_generic_to_shared(smem);
    asm volatile("cp.async.cg.shared.global [%0], [%1], 16;" :: "r"(s), "l"(gmem));
}
#define CP_COMMIT() asm volatile("cp.async.commit_group;")
#define CP_WAIT1()  asm volatile("cp.async.wait_group 1;")

// ---------------------------------------------------------------------------
__global__ __launch_bounds__(256) void round_tf32_kernel(
    const float* __restrict__ in, float* __restrict__ out, int n4)
{
    int i = blockIdx.x * blockDim.x + threadIdx.x;
    if (i < n4) {
        float4 v = ((const float4*)in)[i];
        v.x = to_tf32f(v.x); v.y = to_tf32f(v.y);
        v.z = to_tf32f(v.z); v.w = to_tf32f(v.w);
        ((float4*)out)[i] = v;
    }
}

// ---------------------------------------------------------------------------
// C[M,N] = A[M,K] @ B[K,N] + bias.  A,B pre-rounded tf32.  cp.async 2-stage.
// Block 128x64, 256 thr = 8 warps (4m x 2n), warp tile 32x32, k-step 16.
// MODE: 0 plain fp32 out; 1 rounded; 2 rounded*0.125; 3 rounded transposed.
// ---------------------------------------------------------------------------
template<int MODE>
__global__ __launch_bounds__(256) void gemm_tf32(
    const float* __restrict__ A, const float* __restrict__ B,
    const float* __restrict__ bias, float* __restrict__ C,
    int M, int N, int K)
{
    __shared__ float As[2][128][20];   // [m][k] pad 20 -> conflict-free A frags
    __shared__ float Bs[2][16][72];    // [k][n] pad 72

    const int tid = threadIdx.x;
    const int lane = tid & 31, wid = tid >> 5;
    const int wm = wid >> 1, wn = wid & 1;
    const int row0 = blockIdx.y * 128, col0 = blockIdx.x * 64;
    const int lr = lane >> 2, lc = lane & 3;

    auto load_stage = [&](int buf, int k0) {
        #pragma unroll
        for (int i = 0; i < 2; i++) {                 // A: 512 x 16B
            int s = tid + i * 256;
            int r = s >> 2, o = (s & 3) * 4;
            cp16(&As[buf][r][o], &A[(row0 + r) * K + k0 + o]);
        }
        {                                              // B: 256 x 16B
            int kk = tid >> 4, o = (tid & 15) * 4;
            cp16(&Bs[buf][kk][o], &B[(k0 + kk) * N + col0 + o]);
        }
    };

    float acc[2][4][4] = {};
    load_stage(0, 0);
    CP_COMMIT();

    for (int k0 = 0; k0 < K; k0 += 16) {
        int buf = (k0 >> 4) & 1;
        if (k0 + 16 < K) load_stage(buf ^ 1, k0 + 16);
        CP_COMMIT();
        CP_WAIT1();
        __syncthreads();

        #pragma unroll
        for (int ks = 0; ks < 2; ks++) {
            uint32_t a[2][4], b[4][2];
            #pragma unroll
            for (int mi = 0; mi < 2; mi++) {
                int m0 = wm * 32 + mi * 16;
                a[mi][0] = __float_as_uint(As[buf][m0 + lr    ][ks*8 + lc    ]);
                a[mi][1] = __float_as_uint(As[buf][m0 + lr + 8][ks*8 + lc    ]);
                a[mi][2] = __float_as_uint(As[buf][m0 + lr    ][ks*8 + lc + 4]);
                a[mi][3] = __float_as_uint(As[buf][m0 + lr + 8][ks*8 + lc + 4]);
            }
            #pragma unroll
            for (int ni = 0; ni < 4; ni++) {
                int n0 = wn * 32 + ni * 8;
                b[ni][0] = __float_as_uint(Bs[buf][ks*8 + lc    ][n0 + lr]);
                b[ni][1] = __float_as_uint(Bs[buf][ks*8 + lc + 4][n0 + lr]);
            }
            #pragma unroll
            for (int mi = 0; mi < 2; mi++)
                #pragma unroll
                for (int ni = 0; ni < 4; ni++)
                    mma_tf32(acc[mi][ni], a[mi], b[ni]);
        }
        __syncthreads();
    }

    #pragma unroll
    for (int mi = 0; mi < 2; mi++) {
        #pragma unroll
        for (int ni = 0; ni < 4; ni++) {
            int r = row0 + wm*32 + mi*16 + lr;
            int c = col0 + wn*32 + ni*8 + 2*lc;
            float v00 = acc[mi][ni][0] + bias[c];
            float v01 = acc[mi][ni][1] + bias[c+1];
            float v10 = acc[mi][ni][2] + bias[c];
            float v11 = acc[mi][ni][3] + bias[c+1];
            if (MODE == 0) {
                C[r*N + c] = v00;        C[r*N + c + 1] = v01;
                C[(r+8)*N + c] = v10;    C[(r+8)*N + c + 1] = v11;
            } else if (MODE == 1) {
                C[r*N + c] = to_tf32f(v00);        C[r*N + c + 1] = to_tf32f(v01);
                C[(r+8)*N + c] = to_tf32f(v10);    C[(r+8)*N + c + 1] = to_tf32f(v11);
            } else if (MODE == 2) {
                C[r*N + c] = to_tf32f(v00 * 0.125f);        C[r*N + c + 1] = to_tf32f(v01 * 0.125f);
                C[(r+8)*N + c] = to_tf32f(v10 * 0.125f);    C[(r+8)*N + c + 1] = to_tf32f(v11 * 0.125f);
            } else {  // transposed: C[c][r], C has M columns per row c
                C[c*M + r]         = to_tf32f(v00);
                C[(c+1)*M + r]     = to_tf32f(v01);
                C[c*M + r + 8]     = to_tf32f(v10);
                C[(c+1)*M + r + 8] = to_tf32f(v11);
            }
        }
    }
}

// ---------------------------------------------------------------------------
// Flash attention, tf32 mma, cp.async double-buffered K/V, no in-kernel cvt.
// grid = (64 q-tiles, 16 heads), 128 threads = 4 warps; warp owns 16 q-rows.
// ---------------------------------------------------------------------------
__global__ __launch_bounds__(128) void gqa_attn_tf32()
{
    __shared__ float Ks[2][64][40];   // [d][key], from g_Kt (contiguous rows)
    __shared__ float Vs[2][32][72];   // [key][d]
    __shared__ float Ps[64][36];      // [row][key]

    const int h = blockIdx.y, kvh = h >> 2;
    const int q0 = blockIdx.x * 64;
    const int tid = threadIdx.x;
    const int lane = tid & 31, wid = tid >> 5;
    const int lr = lane >> 2, lc = lane & 3;
    const int m_base = wid * 16;

    auto load_tile = [&](int k0, int buf) {
        #pragma unroll
        for (int i = 0; i < 4; i++) {                 // K: 64 rows x 128B
            int s = tid + i * 128;
            int d = s >> 3, o = (s & 7) * 4;
            cp16(&Ks[buf][d][o], &g_Kt[(kvh*HD + d) * L_SEQ + k0 + o]);
        }
        #pragma unroll
        for (int i = 0; i < 4; i++) {                 // V: 32 rows x 256B
            int s = tid + i * 128;
            int key = s >> 4, o = (s & 15) * 4;
            cp16(&Vs[buf][key][o], &g_V[(k0 + key) * KV_DIM + kvh*HD + o]);
        }
    };

    // Q fragments: pre-scaled + pre-rounded in gmem, plain loads
    uint32_t qa[8][4];
    {
        const float* Qb = g_Q + (q0 + m_base) * D_MODEL + h * HD;
        #pragma unroll
        for (int ks = 0; ks < 8; ks++) {
            qa[ks][0] = __float_as_uint(Qb[(lr    )*D_MODEL + ks*8 + lc    ]);
            qa[ks][1] = __float_as_uint(Qb[(lr + 8)*D_MODEL + ks*8 + lc    ]);
            qa[ks][2] = __float_as_uint(Qb[(lr    )*D_MODEL + ks*8 + lc + 4]);
            qa[ks][3] = __float_as_uint(Qb[(lr + 8)*D_MODEL + ks*8 + lc + 4]);
        }
    }

    float o[8][4] = {};
    float m0 = -1e30f, m1 = -1e30f, l0 = 0.f, l1 = 0.f;

    load_tile(0, 0);
    CP_COMMIT();

    for (int k0 = 0; k0 < L_SEQ; k0 += 32) {
        int buf = (k0 >> 5) & 1;
        if (k0 + 32 < L_SEQ) load_tile(k0 + 32, buf ^ 1);
        CP_COMMIT();
        CP_WAIT1();
        __syncthreads();

        // S = Q @ K^T   (16 x 32 per warp)
        float s[4][4] = {};
        #pragma unroll
        for (int ks = 0; ks < 8; ks++) {
            uint32_t b[4][2];
            #pragma unroll
            for (int nt = 0; nt < 4; nt++) {
                b[nt][0] = __float_as_uint(Ks[buf][ks*8 + lc    ][nt*8 + lr]);
                b[nt][1] = __float_as_uint(Ks[buf][ks*8 + lc + 4][nt*8 + lr]);
            }
            #pragma unroll
            for (int nt = 0; nt < 4; nt++)
                mma_tf32(s[nt], qa[ks], b[nt]);
        }

        // Online softmax (rows lr, lr+8 of this warp's 16)
        float mx0 = s[0][0], mx1 = s[0][2];
        #pragma unroll
        for (int nt = 0; nt < 4; nt++) {
            mx0 = fmaxf(mx0, fmaxf(s[nt][0], s[nt][1]));
            mx1 = fmaxf(mx1, fmaxf(s[nt][2], s[nt][3]));
        }
        mx0 = fmaxf(mx0, __shfl_xor_sync(~0u, mx0, 1));
        mx0 = fmaxf(mx0, __shfl_xor_sync(~0u, mx0, 2));
        mx1 = fmaxf(mx1, __shfl_xor_sync(~0u, mx1, 1));
        mx1 = fmaxf(mx1, __shfl_xor_sync(~0u, mx1, 2));
        float nm0 = fmaxf(m0, mx0), nm1 = fmaxf(m1, mx1);
        float cr0 = __expf(m0 - nm0), cr1 = __expf(m1 - nm1);
        float ls0 = 0.f, ls1 = 0.f;
        #pragma unroll
        for (int nt = 0; nt < 4; nt++) {
            s[nt][0] = __expf(s[nt][0] - nm0); ls0 += s[nt][0];
            s[nt][1] = __expf(s[nt][1] - nm0); ls0 += s[nt][1];
            s[nt][2] = __expf(s[nt][2] - nm1); ls1 += s[nt][2];
            s[nt][3] = __expf(s[nt][3] - nm1); ls1 += s[nt][3];
        }
        ls0 += __shfl_xor_sync(~0u, ls0, 1); ls0 += __shfl_xor_sync(~0u, ls0, 2);
        ls1 += __shfl_xor_sync(~0u, ls1, 1); ls1 += __shfl_xor_sync(~0u, ls1, 2);
        l0 = l0 * cr0 + ls0; l1 = l1 * cr1 + ls1;
        m0 = nm0; m1 = nm1;
        #pragma unroll
        for (int nt = 0; nt < 8; nt++) {
            o[nt][0] *= cr0; o[nt][1] *= cr0; o[nt][2] *= cr1; o[nt][3] *= cr1;
        }

        // Stage P (warp-local; mma truncates tf32 operands, no cvt needed)
        #pragma unroll
        for (int nt = 0; nt < 4; nt++) {
            Ps[m_base + lr    ][nt*8 + 2*lc    ] = s[nt][0];
            Ps[m_base + lr    ][nt*8 + 2*lc + 1] = s[nt][1];
            Ps[m_base + lr + 8][nt*8 + 2*lc    ] = s[nt][2];
            Ps[m_base + lr + 8][nt*8 + 2*lc + 1] = s[nt][3];
        }
        __syncwarp();

        // O += P @ V   (16 x 64 per warp, k=32)
        #pragma unroll
        for (int ks = 0; ks < 4; ks++) {
            uint32_t a[4];
            a[0] = __float_as_uint(Ps[m_base + lr    ][ks*8 + lc    ]);
            a[1] = __float_as_uint(Ps[m_base + lr + 8][ks*8 + lc    ]);
            a[2] = __float_as_uint(Ps[m_base + lr    ][ks*8 + lc + 4]);
            a[3] = __float_as_uint(Ps[m_base + lr + 8][ks*8 + lc + 4]);
            #pragma unroll
            for (int nt = 0; nt < 8; nt++) {
                uint32_t b[2];
                b[0] = __float_as_uint(Vs[buf][ks*8 + lc    ][nt*8 + lr]);
                b[1] = __float_as_uint(Vs[buf][ks*8 + lc + 4][nt*8 + lr]);
                mma_tf32(o[nt], a, b);
            }
        }
        __syncthreads();
    }

    // Epilogue: rounded tf32 so the O-projection consumes it directly
    float inv0 = 1.f / l0, inv1 = 1.f / l1;
    float* Ob = g_A + (q0 + m_base) * D_MODEL + h * HD;
    #pragma unroll
    for (int nt = 0; nt < 8; nt++) {
        Ob[(lr    )*D_MODEL + nt*8 + 2*lc    ] = to_tf32f(o[nt][0] * inv0);
        Ob[(lr    )*D_MODEL + nt*8 + 2*lc + 1] = to_tf32f(o[nt][1] * inv0);
        Ob[(lr + 8)*D_MODEL + nt*8 + 2*lc    ] = to_tf32f(o[nt][2] * inv1);
        Ob[(lr + 8)*D_MODEL + nt*8 + 2*lc + 1] = to_tf32f(o[nt][3] * inv1);
    }
}

// ---------------------------------------------------------------------------
extern "C" void kernel_launch(void* const* d_in, const int* in_sizes, int n_in,
                              void* d_out, int out_size)
{
    const float* x  = (const float*)d_in[0];
    const float* Wq = (const float*)d_in[1];
    const float* bq = (const float*)d_in[2];
    const float* Wk = (const float*)d_in[3];
    const float* bk = (const float*)d_in[4];
    const float* Wv = (const float*)d_in[5];
    const float* bv = (const float*)d_in[6];
    const float* Wo = (const float*)d_in[7];
    const float* bo = (const float*)d_in[8];
    float* out = (float*)d_out;

    float *X32, *Wq32, *Wk32, *Wv32, *Wo32, *Qp, *Ktp, *Vp, *Ap;
    cudaGetSymbolAddress((void**)&X32,  g_X32);
    cudaGetSymbolAddress((void**)&Wq32, g_Wq32);
    cudaGetSymbolAddress((void**)&Wk32, g_Wk32);
    cudaGetSymbolAddress((void**)&Wv32, g_Wv32);
    cudaGetSymbolAddress((void**)&Wo32, g_Wo32);
    cudaGetSymbolAddress((void**)&Qp,   g_Q);
    cudaGetSymbolAddress((void**)&Ktp,  g_Kt);
    cudaGetSymbolAddress((void**)&Vp,   g_V);
    cudaGetSymbolAddress((void**)&Ap,   g_A);

    // Pre-round inputs/weights to tf32 (removes all cvt from hot loops)
    round_tf32_kernel<<<L_SEQ*D_MODEL/4/256, 256>>>(x,  X32,  L_SEQ*D_MODEL/4);
    round_tf32_kernel<<<D_MODEL*D_MODEL/4/256, 256>>>(Wq, Wq32, D_MODEL*D_MODEL/4);
    round_tf32_kernel<<<D_MODEL*KV_DIM/4/256, 256>>>(Wk, Wk32, D_MODEL*KV_DIM/4);
    round_tf32_kernel<<<D_MODEL*KV_DIM/4/256, 256>>>(Wv, Wv32, D_MODEL*KV_DIM/4);
    round_tf32_kernel<<<D_MODEL*D_MODEL/4/256, 256>>>(Wo, Wo32, D_MODEL*D_MODEL/4);

    // Projections (Q pre-scaled; K transposed; all rounded for downstream)
    gemm_tf32<2><<<dim3(D_MODEL/64, L_SEQ/128), 256>>>(X32, Wq32, bq, Qp,  L_SEQ, D_MODEL, D_MODEL);
    gemm_tf32<3><<<dim3(KV_DIM /64, L_SEQ/128), 256>>>(X32, Wk32, bk, Ktp, L_SEQ, KV_DIM,  D_MODEL);
    gemm_tf32<1><<<dim3(KV_DIM /64, L_SEQ/128), 256>>>(X32, Wv32, bv, Vp,  L_SEQ, KV_DIM,  D_MODEL);
    // Attention
    gqa_attn_tf32<<<dim3(L_SEQ/64, NHEADS), 128>>>();
    // Output projection
    gemm_tf32<0><<<dim3(D_MODEL/64, L_SEQ/128), 256>>>(Ap, Wo32, bo, out, L_SEQ, D_MODEL, D_MODEL);
}